// round 14
// baseline (speedup 1.0000x reference)
#include <cuda_runtime.h>
#include <cuda_fp16.h>
#include <cstdint>

#define NN 100000
#define NE 1600000
#define SCAN_TILE 1024
#define SCAN_NB ((NN + SCAN_TILE - 1) / SCAN_TILE)   // 98

#define APAD 136   // As row stride (halves)
#define WPAD 40    // Wts row stride (halves)

// m16n8k16 fp16 MMA, fp32 accumulate (sm_80+ PTX, works on compute_103)
#define MMA16816(c0, c1, c2, c3, a0, a1, a2, a3, b0, b1) \
    asm volatile("mma.sync.aligned.m16n8k16.row.col.f32.f16.f16.f32 " \
        "{%0,%1,%2,%3}, {%4,%5,%6,%7}, {%8,%9}, {%0,%1,%2,%3};" \
        : "+f"(c0), "+f"(c1), "+f"(c2), "+f"(c3) \
        : "r"(a0), "r"(a1), "r"(a2), "r"(a3), "r"(b0), "r"(b1))

// ---------------- device scratch ----------------
__device__ int     g_deg_in[NN];
__device__ int     g_deg_out[NN];
__device__ int     g_cursor[NN];
__device__ float   g_norm_src[NN];
__device__ float   g_norm_dst[NN];
__device__ int     g_row_ptr[NN + 1];
__device__ int     g_csr_src[NE];
__device__ int     g_blk_sum[SCAN_NB];
__device__ int     g_blk_off[SCAN_NB];
__device__ __half2 g_emb_h[(size_t)NN * 64];   // emb * norm_src, fp16
__device__ __half2 g_agg_h[(size_t)NN * 64];   // spmm1 result, fp16
__device__ __half2 g_t_h[(size_t)NN * 32];     // (h1@W2)*norm_src, fp16

// ---------------- setup ----------------
__global__ void k_zero(int n) {
    int i = blockIdx.x * blockDim.x + threadIdx.x;
    if (i < n) { g_deg_in[i] = 0; g_deg_out[i] = 0; g_cursor[i] = 0; }
}

__global__ void k_degree(const int* __restrict__ src,
                         const int* __restrict__ dst, int e2, int e) {
    int i = blockIdx.x * blockDim.x + threadIdx.x;
    if (i < e2) {
        int2 s = ((const int2*)src)[i];
        int2 d = ((const int2*)dst)[i];
        if ((unsigned)s.x < NN) atomicAdd(&g_deg_out[s.x], 1);
        if ((unsigned)s.y < NN) atomicAdd(&g_deg_out[s.y], 1);
        if ((unsigned)d.x < NN) atomicAdd(&g_deg_in[d.x], 1);
        if ((unsigned)d.y < NN) atomicAdd(&g_deg_in[d.y], 1);
    } else if (i == e2 && (e & 1)) {
        int s = src[e - 1], d = dst[e - 1];
        if ((unsigned)s < NN) atomicAdd(&g_deg_out[s], 1);
        if ((unsigned)d < NN) atomicAdd(&g_deg_in[d], 1);
    }
}

// emb * norm_src -> half2; 8 floats per thread
__global__ void k_prep(const float* __restrict__ emb, int n16) {
    int i = blockIdx.x * blockDim.x + threadIdx.x;
    if (i < n16) {
        int r = i >> 4;
        float4 v0 = ((const float4*)emb)[2 * i];
        float4 v1 = ((const float4*)emb)[2 * i + 1];
        float ns = g_norm_src[r];
        uint4 o;
        *(__half2*)&o.x = __floats2half2_rn(v0.x * ns, v0.y * ns);
        *(__half2*)&o.y = __floats2half2_rn(v0.z * ns, v0.w * ns);
        *(__half2*)&o.z = __floats2half2_rn(v1.x * ns, v1.y * ns);
        *(__half2*)&o.w = __floats2half2_rn(v1.z * ns, v1.w * ns);
        ((uint4*)g_emb_h)[i] = o;
    }
}

// ---------------- scan phase 1 + norm computation (fused) ----------------
__global__ void __launch_bounds__(256)
k_scan_partial(int n) {
    __shared__ int sm[256];
    int t = threadIdx.x;
    int base = blockIdx.x * SCAN_TILE + t * 4;
    int s = 0;
#pragma unroll
    for (int j = 0; j < 4; j++) {
        int i = base + j;
        if (i < n) {
            int din = g_deg_in[i];
            s += din;
            int dout = g_deg_out[i];
            if (dout < 1) dout = 1;
            if (din  < 1) din  = 1;
            g_norm_src[i] = rsqrtf((float)dout);
            g_norm_dst[i] = rsqrtf((float)din);
        }
    }
    sm[t] = s;
    __syncthreads();
    for (int off = 128; off > 0; off >>= 1) {
        if (t < off) sm[t] += sm[t + off];
        __syncthreads();
    }
    if (t == 0) g_blk_sum[blockIdx.x] = sm[0];
}

__global__ void __launch_bounds__(128)
k_scan_blk(int n, int e) {
    __shared__ int sm[128];
    int t = threadIdx.x;
    int v = (t < SCAN_NB) ? g_blk_sum[t] : 0;
    sm[t] = v;
    __syncthreads();
    for (int off = 1; off < 128; off <<= 1) {
        int add = 0;
        if (t >= off) add = sm[t - off];
        __syncthreads();
        sm[t] += add;
        __syncthreads();
    }
    if (t < SCAN_NB) g_blk_off[t] = sm[t] - v;
    if (t == 0) g_row_ptr[n] = e;
}

__global__ void __launch_bounds__(256)
k_scan_final(int n) {
    __shared__ int sm[256];
    int t = threadIdx.x;
    int base = blockIdx.x * SCAN_TILE + t * 4;
    int d[4];
    int s = 0;
#pragma unroll
    for (int j = 0; j < 4; j++) {
        int i = base + j;
        d[j] = (i < n) ? g_deg_in[i] : 0;
        s += d[j];
    }
    sm[t] = s;
    __syncthreads();
    for (int off = 1; off < 256; off <<= 1) {
        int add = 0;
        if (t >= off) add = sm[t - off];
        __syncthreads();
        sm[t] += add;
        __syncthreads();
    }
    int run = g_blk_off[blockIdx.x] + sm[t] - s;
#pragma unroll
    for (int j = 0; j < 4; j++) {
        int i = base + j;
        if (i < n) g_row_ptr[i] = run;
        run += d[j];
    }
}

__global__ void k_fill(const int* __restrict__ src,
                       const int* __restrict__ dst, int e2, int e) {
    int i = blockIdx.x * blockDim.x + threadIdx.x;
    if (i < e2) {
        int2 s = ((const int2*)src)[i];
        int2 d = ((const int2*)dst)[i];
        if ((unsigned)d.x < NN && (unsigned)s.x < NN) {
            int pos = g_row_ptr[d.x] + atomicAdd(&g_cursor[d.x], 1);
            g_csr_src[pos] = s.x;
        }
        if ((unsigned)d.y < NN && (unsigned)s.y < NN) {
            int pos = g_row_ptr[d.y] + atomicAdd(&g_cursor[d.y], 1);
            g_csr_src[pos] = s.y;
        }
    } else if (i == e2 && (e & 1)) {
        int s = src[e - 1], d = dst[e - 1];
        if ((unsigned)d < NN && (unsigned)s < NN) {
            int pos = g_row_ptr[d] + atomicAdd(&g_cursor[d], 1);
            g_csr_src[pos] = s;
        }
    }
}

// ---------------- SpMM 1: pairwise HADD2 then fp32 accumulate ----------------
__global__ void k_spmm1(int n) {
    int w = (blockIdx.x * blockDim.x + threadIdx.x) >> 5;
    int lane = threadIdx.x & 31;
    if (w >= n) return;
    int beg = g_row_ptr[w];
    int end = g_row_ptr[w + 1];
    const uint2* eh = (const uint2*)g_emb_h;   // row = 32 uint2
    float4 acc = make_float4(0.f, 0.f, 0.f, 0.f);
    int ed = beg;
    for (; ed + 3 < end; ed += 4) {
        int s0 = g_csr_src[ed];
        int s1 = g_csr_src[ed + 1];
        int s2 = g_csr_src[ed + 2];
        int s3 = g_csr_src[ed + 3];
        uint2 v0 = eh[(size_t)s0 * 32 + lane];
        uint2 v1 = eh[(size_t)s1 * 32 + lane];
        uint2 v2 = eh[(size_t)s2 * 32 + lane];
        uint2 v3 = eh[(size_t)s3 * 32 + lane];
        __half2 px01 = __hadd2(*(__half2*)&v0.x, *(__half2*)&v1.x);
        __half2 py01 = __hadd2(*(__half2*)&v0.y, *(__half2*)&v1.y);
        __half2 px23 = __hadd2(*(__half2*)&v2.x, *(__half2*)&v3.x);
        __half2 py23 = __hadd2(*(__half2*)&v2.y, *(__half2*)&v3.y);
        float2 a01 = __half22float2(px01), b01 = __half22float2(py01);
        float2 a23 = __half22float2(px23), b23 = __half22float2(py23);
        acc.x += a01.x + a23.x;
        acc.y += a01.y + a23.y;
        acc.z += b01.x + b23.x;
        acc.w += b01.y + b23.y;
    }
    for (; ed < end; ed++) {
        int s0 = g_csr_src[ed];
        uint2 v0 = eh[(size_t)s0 * 32 + lane];
        float2 a0 = __half22float2(*(__half2*)&v0.x);
        float2 b0 = __half22float2(*(__half2*)&v0.y);
        acc.x += a0.x; acc.y += a0.y; acc.z += b0.x; acc.w += b0.y;
    }
    float nd = g_norm_dst[w];
    uint2 o;
    *(__half2*)&o.x = __floats2half2_rn(acc.x * nd, acc.y * nd);
    *(__half2*)&o.y = __floats2half2_rn(acc.z * nd, acc.w * nd);
    ((uint2*)g_agg_h)[(size_t)w * 32 + lane] = o;
}

// ---------------- fused GEMM via HMMA (mma.sync m16n8k16) ----------------
__global__ void __launch_bounds__(256)
k_gemm_mma(const float* __restrict__ W1, const float* __restrict__ b1,
           const float* __restrict__ W2, int n) {
    __shared__ __half As[128 * APAD];    // 34.8KB
    __shared__ __half Wts[128 * WPAD];   // 10.2KB, [n][k] transposed chunks
    __shared__ float b1s[128];

    const int tid = threadIdx.x;
    const int lane = tid & 31;
    const int wid = tid >> 5;
    const int row0 = blockIdx.x * 128;
    const int m0 = wid * 16;
    const int r = lane >> 2;          // 0..7
    const int qc = (lane & 3) * 2;    // 0,2,4,6

    // load A tile (fp16, from g_agg_h), zero-pad OOB rows
    for (int i = tid; i < 128 * 32; i += 256) {
        int row = i >> 5, q = i & 31;
        int gr = row0 + row;
        uint2 v = make_uint2(0u, 0u);
        if (gr < n) v = ((const uint2*)g_agg_h)[(size_t)gr * 32 + q];
        *(uint2*)&As[row * APAD + q * 4] = v;
    }
    if (tid < 128) b1s[tid] = b1[tid];

    // ---- phase 1: 16x128 per warp, K=128 ----
    float acc[16][4];
#pragma unroll
    for (int t2 = 0; t2 < 16; t2++)
#pragma unroll
        for (int j = 0; j < 4; j++) acc[t2][j] = 0.f;

    for (int kc = 0; kc < 4; kc++) {
        __syncthreads();
        for (int i = tid; i < 32 * 128; i += 256) {
            int kl = i >> 7, nn = i & 127;
            Wts[nn * WPAD + kl] = __float2half(W1[(kc * 32 + kl) * 128 + nn]);
        }
        __syncthreads();
#pragma unroll
        for (int ks = 0; ks < 2; ks++) {
            int kb = kc * 32 + ks * 16;
            uint32_t a0 = *(uint32_t*)&As[(m0 + r) * APAD + kb + qc];
            uint32_t a1 = *(uint32_t*)&As[(m0 + r + 8) * APAD + kb + qc];
            uint32_t a2 = *(uint32_t*)&As[(m0 + r) * APAD + kb + qc + 8];
            uint32_t a3 = *(uint32_t*)&As[(m0 + r + 8) * APAD + kb + qc + 8];
            int kw = ks * 16;
#pragma unroll
            for (int nt = 0; nt < 16; nt++) {
                uint32_t b0 = *(uint32_t*)&Wts[(nt * 8 + r) * WPAD + kw + qc];
                uint32_t b1f = *(uint32_t*)&Wts[(nt * 8 + r) * WPAD + kw + qc + 8];
                MMA16816(acc[nt][0], acc[nt][1], acc[nt][2], acc[nt][3],
                         a0, a1, a2, a3, b0, b1f);
            }
        }
    }

    // epilogue 1: relu + bias, write h1 fp16 into As (own rows only)
#pragma unroll
    for (int nt = 0; nt < 16; nt++) {
        int c = nt * 8 + qc;
        float x0 = fmaxf(acc[nt][0] + b1s[c],     0.f);
        float x1 = fmaxf(acc[nt][1] + b1s[c + 1], 0.f);
        float x2 = fmaxf(acc[nt][2] + b1s[c],     0.f);
        float x3 = fmaxf(acc[nt][3] + b1s[c + 1], 0.f);
        *(__half2*)&As[(m0 + r) * APAD + c]     = __floats2half2_rn(x0, x1);
        *(__half2*)&As[(m0 + r + 8) * APAD + c] = __floats2half2_rn(x2, x3);
    }

    // ---- phase 2: 16x64 per warp, K=128 ----
    float acc2[8][4];
#pragma unroll
    for (int t2 = 0; t2 < 8; t2++)
#pragma unroll
        for (int j = 0; j < 4; j++) acc2[t2][j] = 0.f;

    for (int kc = 0; kc < 4; kc++) {
        __syncthreads();
        for (int i = tid; i < 32 * 64; i += 256) {
            int kl = i >> 6, nn = i & 63;
            Wts[nn * WPAD + kl] = __float2half(W2[(kc * 32 + kl) * 64 + nn]);
        }
        __syncthreads();
#pragma unroll
        for (int ks = 0; ks < 2; ks++) {
            int kb = kc * 32 + ks * 16;
            uint32_t a0 = *(uint32_t*)&As[(m0 + r) * APAD + kb + qc];
            uint32_t a1 = *(uint32_t*)&As[(m0 + r + 8) * APAD + kb + qc];
            uint32_t a2 = *(uint32_t*)&As[(m0 + r) * APAD + kb + qc + 8];
            uint32_t a3 = *(uint32_t*)&As[(m0 + r + 8) * APAD + kb + qc + 8];
            int kw = ks * 16;
#pragma unroll
            for (int nt = 0; nt < 8; nt++) {
                uint32_t b0 = *(uint32_t*)&Wts[(nt * 8 + r) * WPAD + kw + qc];
                uint32_t b1f = *(uint32_t*)&Wts[(nt * 8 + r) * WPAD + kw + qc + 8];
                MMA16816(acc2[nt][0], acc2[nt][1], acc2[nt][2], acc2[nt][3],
                         a0, a1, a2, a3, b0, b1f);
            }
        }
    }

    // epilogue 2: * norm_src, fp16 store
    {
        int gr0 = row0 + m0 + r;
        int gr1 = gr0 + 8;
        float ns0 = (gr0 < n) ? g_norm_src[gr0] : 0.f;
        float ns1 = (gr1 < n) ? g_norm_src[gr1] : 0.f;
#pragma unroll
        for (int nt = 0; nt < 8; nt++) {
            int c = nt * 8 + qc;   // even
            if (gr0 < n)
                g_t_h[(size_t)gr0 * 32 + (c >> 1)] =
                    __floats2half2_rn(acc2[nt][0] * ns0, acc2[nt][1] * ns0);
            if (gr1 < n)
                g_t_h[(size_t)gr1 * 32 + (c >> 1)] =
                    __floats2half2_rn(acc2[nt][2] * ns1, acc2[nt][3] * ns1);
        }
    }
}

// ---------------- SpMM 2 (pairwise HADD2, fp32 accumulate) ----------------
__global__ void k_spmm2(const float* __restrict__ b2, float* __restrict__ out, int n) {
    int w = (blockIdx.x * blockDim.x + threadIdx.x) >> 5;
    int lane = threadIdx.x & 31;
    if (w >= n) return;
    int beg = g_row_ptr[w];
    int end = g_row_ptr[w + 1];
    float2 acc = make_float2(0.f, 0.f);
    int ed = beg;
    for (; ed + 3 < end; ed += 4) {
        int s0 = g_csr_src[ed];
        int s1 = g_csr_src[ed + 1];
        int s2 = g_csr_src[ed + 2];
        int s3 = g_csr_src[ed + 3];
        __half2 t0 = g_t_h[(size_t)s0 * 32 + lane];
        __half2 t1 = g_t_h[(size_t)s1 * 32 + lane];
        __half2 t2 = g_t_h[(size_t)s2 * 32 + lane];
        __half2 t3 = g_t_h[(size_t)s3 * 32 + lane];
        float2 p01 = __half22float2(__hadd2(t0, t1));
        float2 p23 = __half22float2(__hadd2(t2, t3));
        acc.x += p01.x + p23.x;
        acc.y += p01.y + p23.y;
    }
    for (; ed < end; ed++) {
        int s0 = g_csr_src[ed];
        float2 v0 = __half22float2(g_t_h[(size_t)s0 * 32 + lane]);
        acc.x += v0.x;
        acc.y += v0.y;
    }
    float nd = g_norm_dst[w];
    float2 bb = ((const float2*)b2)[lane];
    float2 o;
    o.x = fmaf(acc.x, nd, bb.x);
    o.y = fmaf(acc.y, nd, bb.y);
    ((float2*)out)[(size_t)w * 32 + lane] = o;
}

// ---------------- launch (dup-gemm at slot 4 for profiling) ----------------
extern "C" void kernel_launch(void* const* d_in, const int* in_sizes, int n_in,
                              void* d_out, int out_size) {
    const int* src = (const int*)d_in[1];
    const int* dst = (const int*)d_in[2];
    const float* emb = (const float*)d_in[3];
    const float* W1  = (const float*)d_in[4];
    const float* b1  = (const float*)d_in[5];
    const float* W2  = (const float*)d_in[6];
    const float* b2  = (const float*)d_in[7];
    float* out = (float*)d_out;

    const int n = in_sizes[0];
    const int e = in_sizes[1];
    const int e2 = e >> 1;

    k_zero<<<(n + 255) / 256, 256>>>(n);
    k_degree<<<(e2 + 256) / 256, 256>>>(src, dst, e2, e);
    k_scan_partial<<<SCAN_NB, 256>>>(n);     // also computes norms

    // MEASUREMENT: duplicate gemm in the ncu-profiled 4th slot.
    // Reads stale-but-deterministic g_agg_h/g_norm_src; writes g_t_h which the
    // real gemm below fully overwrites. Output unchanged; adds gemm_time to dur.
    k_gemm_mma<<<(n + 127) / 128, 256>>>(W1, b1, W2, n);

    k_prep<<<(n * 16 + 255) / 256, 256>>>(emb, n * 16);
    k_scan_blk<<<1, 128>>>(n, e);
    k_scan_final<<<SCAN_NB, 256>>>(n);
    k_fill<<<(e2 + 256) / 256, 256>>>(src, dst, e2, e);

    int warps_grid = (n * 32 + 255) / 256;
    k_spmm1<<<warps_grid, 256>>>(n);
    k_gemm_mma<<<(n + 127) / 128, 256>>>(W1, b1, W2, n);
    k_spmm2<<<warps_grid, 256>>>(b2, out, n);
}

// round 15
// speedup vs baseline: 1.2103x; 1.2103x over previous
#include <cuda_runtime.h>
#include <cuda_fp16.h>
#include <cstdint>

#define NN 100000
#define NE 1600000
#define SCAN_TILE 1024
#define SCAN_NB ((NN + SCAN_TILE - 1) / SCAN_TILE)   // 98

#define APAD 136   // As row stride (halves)
#define WPAD 40    // Wts row stride (halves)

// m16n8k16 fp16 MMA, fp32 accumulate
#define MMA16816(c0, c1, c2, c3, a0, a1, a2, a3, b0, b1) \
    asm volatile("mma.sync.aligned.m16n8k16.row.col.f32.f16.f16.f32 " \
        "{%0,%1,%2,%3}, {%4,%5,%6,%7}, {%8,%9}, {%0,%1,%2,%3};" \
        : "+f"(c0), "+f"(c1), "+f"(c2), "+f"(c3) \
        : "r"(a0), "r"(a1), "r"(a2), "r"(a3), "r"(b0), "r"(b1))

// ---------------- device scratch ----------------
__device__ int     g_deg_in[NN];
__device__ int     g_deg_out[NN];
__device__ int     g_cursor[NN];
__device__ float   g_norm_src[NN];
__device__ float   g_norm_dst[NN];
__device__ int     g_row_ptr[NN + 1];
__device__ int     g_csr_src[NE];
__device__ int     g_blk_sum[SCAN_NB];
__device__ int     g_blk_off[SCAN_NB];
__device__ __half2 g_emb_h[(size_t)NN * 64];
__device__ __half2 g_agg_h[(size_t)NN * 64];
__device__ __half2 g_t_h[(size_t)NN * 32];

// ---------------- setup ----------------
__global__ void k_zero(int n) {
    int i = blockIdx.x * blockDim.x + threadIdx.x;
    if (i < n) { g_deg_in[i] = 0; g_deg_out[i] = 0; g_cursor[i] = 0; }
}

__global__ void k_degree(const int* __restrict__ src,
                         const int* __restrict__ dst, int e2, int e) {
    int i = blockIdx.x * blockDim.x + threadIdx.x;
    if (i < e2) {
        int2 s = ((const int2*)src)[i];
        int2 d = ((const int2*)dst)[i];
        if ((unsigned)s.x < NN) atomicAdd(&g_deg_out[s.x], 1);
        if ((unsigned)s.y < NN) atomicAdd(&g_deg_out[s.y], 1);
        if ((unsigned)d.x < NN) atomicAdd(&g_deg_in[d.x], 1);
        if ((unsigned)d.y < NN) atomicAdd(&g_deg_in[d.y], 1);
    } else if (i == e2 && (e & 1)) {
        int s = src[e - 1], d = dst[e - 1];
        if ((unsigned)s < NN) atomicAdd(&g_deg_out[s], 1);
        if ((unsigned)d < NN) atomicAdd(&g_deg_in[d], 1);
    }
}

__global__ void k_prep(const float* __restrict__ emb, int n16) {
    int i = blockIdx.x * blockDim.x + threadIdx.x;
    if (i < n16) {
        int r = i >> 4;
        float4 v0 = ((const float4*)emb)[2 * i];
        float4 v1 = ((const float4*)emb)[2 * i + 1];
        float ns = g_norm_src[r];
        uint4 o;
        *(__half2*)&o.x = __floats2half2_rn(v0.x * ns, v0.y * ns);
        *(__half2*)&o.y = __floats2half2_rn(v0.z * ns, v0.w * ns);
        *(__half2*)&o.z = __floats2half2_rn(v1.x * ns, v1.y * ns);
        *(__half2*)&o.w = __floats2half2_rn(v1.z * ns, v1.w * ns);
        ((uint4*)g_emb_h)[i] = o;
    }
}

__global__ void __launch_bounds__(256)
k_scan_partial(int n) {
    __shared__ int sm[256];
    int t = threadIdx.x;
    int base = blockIdx.x * SCAN_TILE + t * 4;
    int s = 0;
#pragma unroll
    for (int j = 0; j < 4; j++) {
        int i = base + j;
        if (i < n) {
            int din = g_deg_in[i];
            s += din;
            int dout = g_deg_out[i];
            if (dout < 1) dout = 1;
            if (din  < 1) din  = 1;
            g_norm_src[i] = rsqrtf((float)dout);
            g_norm_dst[i] = rsqrtf((float)din);
        }
    }
    sm[t] = s;
    __syncthreads();
    for (int off = 128; off > 0; off >>= 1) {
        if (t < off) sm[t] += sm[t + off];
        __syncthreads();
    }
    if (t == 0) g_blk_sum[blockIdx.x] = sm[0];
}

__global__ void __launch_bounds__(128)
k_scan_blk(int n, int e) {
    __shared__ int sm[128];
    int t = threadIdx.x;
    int v = (t < SCAN_NB) ? g_blk_sum[t] : 0;
    sm[t] = v;
    __syncthreads();
    for (int off = 1; off < 128; off <<= 1) {
        int add = 0;
        if (t >= off) add = sm[t - off];
        __syncthreads();
        sm[t] += add;
        __syncthreads();
    }
    if (t < SCAN_NB) g_blk_off[t] = sm[t] - v;
    if (t == 0) g_row_ptr[n] = e;
}

__global__ void __launch_bounds__(256)
k_scan_final(int n) {
    __shared__ int sm[256];
    int t = threadIdx.x;
    int base = blockIdx.x * SCAN_TILE + t * 4;
    int d[4];
    int s = 0;
#pragma unroll
    for (int j = 0; j < 4; j++) {
        int i = base + j;
        d[j] = (i < n) ? g_deg_in[i] : 0;
        s += d[j];
    }
    sm[t] = s;
    __syncthreads();
    for (int off = 1; off < 256; off <<= 1) {
        int add = 0;
        if (t >= off) add = sm[t - off];
        __syncthreads();
        sm[t] += add;
        __syncthreads();
    }
    int run = g_blk_off[blockIdx.x] + sm[t] - s;
#pragma unroll
    for (int j = 0; j < 4; j++) {
        int i = base + j;
        if (i < n) g_row_ptr[i] = run;
        run += d[j];
    }
}

__global__ void k_fill(const int* __restrict__ src,
                       const int* __restrict__ dst, int e2, int e) {
    int i = blockIdx.x * blockDim.x + threadIdx.x;
    if (i < e2) {
        int2 s = ((const int2*)src)[i];
        int2 d = ((const int2*)dst)[i];
        if ((unsigned)d.x < NN && (unsigned)s.x < NN) {
            int pos = g_row_ptr[d.x] + atomicAdd(&g_cursor[d.x], 1);
            g_csr_src[pos] = s.x;
        }
        if ((unsigned)d.y < NN && (unsigned)s.y < NN) {
            int pos = g_row_ptr[d.y] + atomicAdd(&g_cursor[d.y], 1);
            g_csr_src[pos] = s.y;
        }
    } else if (i == e2 && (e & 1)) {
        int s = src[e - 1], d = dst[e - 1];
        if ((unsigned)d < NN && (unsigned)s < NN) {
            int pos = g_row_ptr[d] + atomicAdd(&g_cursor[d], 1);
            g_csr_src[pos] = s;
        }
    }
}

// ---------------- SpMM 1: pairwise HADD2 then fp32 accumulate ----------------
__global__ void k_spmm1(int n) {
    int w = (blockIdx.x * blockDim.x + threadIdx.x) >> 5;
    int lane = threadIdx.x & 31;
    if (w >= n) return;
    int beg = g_row_ptr[w];
    int end = g_row_ptr[w + 1];
    const uint2* eh = (const uint2*)g_emb_h;
    float4 acc = make_float4(0.f, 0.f, 0.f, 0.f);
    int ed = beg;
    for (; ed + 3 < end; ed += 4) {
        int s0 = g_csr_src[ed];
        int s1 = g_csr_src[ed + 1];
        int s2 = g_csr_src[ed + 2];
        int s3 = g_csr_src[ed + 3];
        uint2 v0 = eh[(size_t)s0 * 32 + lane];
        uint2 v1 = eh[(size_t)s1 * 32 + lane];
        uint2 v2 = eh[(size_t)s2 * 32 + lane];
        uint2 v3 = eh[(size_t)s3 * 32 + lane];
        __half2 px01 = __hadd2(*(__half2*)&v0.x, *(__half2*)&v1.x);
        __half2 py01 = __hadd2(*(__half2*)&v0.y, *(__half2*)&v1.y);
        __half2 px23 = __hadd2(*(__half2*)&v2.x, *(__half2*)&v3.x);
        __half2 py23 = __hadd2(*(__half2*)&v2.y, *(__half2*)&v3.y);
        float2 a01 = __half22float2(px01), b01 = __half22float2(py01);
        float2 a23 = __half22float2(px23), b23 = __half22float2(py23);
        acc.x += a01.x + a23.x;
        acc.y += a01.y + a23.y;
        acc.z += b01.x + b23.x;
        acc.w += b01.y + b23.y;
    }
    for (; ed < end; ed++) {
        int s0 = g_csr_src[ed];
        uint2 v0 = eh[(size_t)s0 * 32 + lane];
        float2 a0 = __half22float2(*(__half2*)&v0.x);
        float2 b0 = __half22float2(*(__half2*)&v0.y);
        acc.x += a0.x; acc.y += a0.y; acc.z += b0.x; acc.w += b0.y;
    }
    float nd = g_norm_dst[w];
    uint2 o;
    *(__half2*)&o.x = __floats2half2_rn(acc.x * nd, acc.y * nd);
    *(__half2*)&o.y = __floats2half2_rn(acc.z * nd, acc.w * nd);
    ((uint2*)g_agg_h)[(size_t)w * 32 + lane] = o;
}

// ---------------- fused GEMM via HMMA — occupancy-optimized ----------------
// 256 thr, 64 rows per block. Warp-pairs share 16 rows, split columns:
//   phase1: warp = 16 rows x 64 cols (col half nh), acc[8][4] (32 regs)
//   phase2: warp = 16 rows x 32 cols, acc2[4][4] (16 regs)
// smem ~28KB, ~70 regs -> 3 blocks/SM (vs 2 before), 1563 blocks.
__global__ void __launch_bounds__(256)
k_gemm_mma(const float* __restrict__ W1, const float* __restrict__ b1,
           const float* __restrict__ W2, int n) {
    __shared__ __half As[64 * APAD];     // 17.4KB
    __shared__ __half Wts[128 * WPAD];   // 10.2KB
    __shared__ float b1s[128];

    const int tid = threadIdx.x;
    const int lane = tid & 31;
    const int wid = tid >> 5;
    const int row0 = blockIdx.x * 64;
    const int m0 = (wid >> 1) * 16;   // rows: warp-pair shares 16 rows
    const int nh = wid & 1;           // column half
    const int r = lane >> 2;          // 0..7
    const int qc = (lane & 3) * 2;    // 0,2,4,6

    // load A tile (64 rows x 32 uint2)
    for (int i = tid; i < 64 * 32; i += 256) {
        int row = i >> 5, q = i & 31;
        int gr = row0 + row;
        uint2 v = make_uint2(0u, 0u);
        if (gr < n) v = ((const uint2*)g_agg_h)[(size_t)gr * 32 + q];
        *(uint2*)&As[row * APAD + q * 4] = v;
    }
    if (tid < 128) b1s[tid] = b1[tid];

    // ---- phase 1: 16 rows x 64 cols per warp, K=128 ----
    const int c0 = nh * 64;
    float acc[8][4];
#pragma unroll
    for (int t2 = 0; t2 < 8; t2++)
#pragma unroll
        for (int j = 0; j < 4; j++) acc[t2][j] = 0.f;

    for (int kc = 0; kc < 4; kc++) {
        __syncthreads();
        for (int i = tid; i < 32 * 128; i += 256) {
            int kl = i >> 7, nn = i & 127;
            Wts[nn * WPAD + kl] = __float2half(W1[(kc * 32 + kl) * 128 + nn]);
        }
        __syncthreads();
#pragma unroll
        for (int ks = 0; ks < 2; ks++) {
            int kb = kc * 32 + ks * 16;
            uint32_t a0 = *(uint32_t*)&As[(m0 + r) * APAD + kb + qc];
            uint32_t a1 = *(uint32_t*)&As[(m0 + r + 8) * APAD + kb + qc];
            uint32_t a2 = *(uint32_t*)&As[(m0 + r) * APAD + kb + qc + 8];
            uint32_t a3 = *(uint32_t*)&As[(m0 + r + 8) * APAD + kb + qc + 8];
            int kw = ks * 16;
#pragma unroll
            for (int nt = 0; nt < 8; nt++) {
                uint32_t b0 = *(uint32_t*)&Wts[(c0 + nt * 8 + r) * WPAD + kw + qc];
                uint32_t b1f = *(uint32_t*)&Wts[(c0 + nt * 8 + r) * WPAD + kw + qc + 8];
                MMA16816(acc[nt][0], acc[nt][1], acc[nt][2], acc[nt][3],
                         a0, a1, a2, a3, b0, b1f);
            }
        }
    }

    // all phase-1 As reads (both warps of each row-pair) must finish before overwrite
    __syncthreads();

    // epilogue 1: relu + bias, h1 fp16 into As (this warp's 16 rows x 64 cols)
#pragma unroll
    for (int nt = 0; nt < 8; nt++) {
        int c = c0 + nt * 8 + qc;
        float x0 = fmaxf(acc[nt][0] + b1s[c],     0.f);
        float x1 = fmaxf(acc[nt][1] + b1s[c + 1], 0.f);
        float x2 = fmaxf(acc[nt][2] + b1s[c],     0.f);
        float x3 = fmaxf(acc[nt][3] + b1s[c + 1], 0.f);
        *(__half2*)&As[(m0 + r) * APAD + c]     = __floats2half2_rn(x0, x1);
        *(__half2*)&As[(m0 + r + 8) * APAD + c] = __floats2half2_rn(x2, x3);
    }

    // ---- phase 2: 16 rows x 32 cols per warp, K=128 ----
    const int c2 = nh * 32;
    float acc2[4][4];
#pragma unroll
    for (int t2 = 0; t2 < 4; t2++)
#pragma unroll
        for (int j = 0; j < 4; j++) acc2[t2][j] = 0.f;

    for (int kc = 0; kc < 4; kc++) {
        __syncthreads();   // first iter: h1 writes visible; later: Wts reuse safe
        for (int i = tid; i < 32 * 64; i += 256) {
            int kl = i >> 6, nn = i & 63;
            Wts[nn * WPAD + kl] = __float2half(W2[(kc * 32 + kl) * 64 + nn]);
        }
        __syncthreads();
#pragma unroll
        for (int ks = 0; ks < 2; ks++) {
            int kb = kc * 32 + ks * 16;
            uint32_t a0 = *(uint32_t*)&As[(m0 + r) * APAD + kb + qc];
            uint32_t a1 = *(uint32_t*)&As[(m0 + r + 8) * APAD + kb + qc];
            uint32_t a2 = *(uint32_t*)&As[(m0 + r) * APAD + kb + qc + 8];
            uint32_t a3 = *(uint32_t*)&As[(m0 + r + 8) * APAD + kb + qc + 8];
            int kw = ks * 16;
#pragma unroll
            for (int nt = 0; nt < 4; nt++) {
                uint32_t b0 = *(uint32_t*)&Wts[(c2 + nt * 8 + r) * WPAD + kw + qc];
                uint32_t b1f = *(uint32_t*)&Wts[(c2 + nt * 8 + r) * WPAD + kw + qc + 8];
                MMA16816(acc2[nt][0], acc2[nt][1], acc2[nt][2], acc2[nt][3],
                         a0, a1, a2, a3, b0, b1f);
            }
        }
    }

    // epilogue 2: * norm_src, fp16 store (16 rows x 32 cols)
    {
        int gr0 = row0 + m0 + r;
        int gr1 = gr0 + 8;
        float ns0 = (gr0 < n) ? g_norm_src[gr0] : 0.f;
        float ns1 = (gr1 < n) ? g_norm_src[gr1] : 0.f;
#pragma unroll
        for (int nt = 0; nt < 4; nt++) {
            int c = c2 + nt * 8 + qc;   // even
            if (gr0 < n)
                g_t_h[(size_t)gr0 * 32 + (c >> 1)] =
                    __floats2half2_rn(acc2[nt][0] * ns0, acc2[nt][1] * ns0);
            if (gr1 < n)
                g_t_h[(size_t)gr1 * 32 + (c >> 1)] =
                    __floats2half2_rn(acc2[nt][2] * ns1, acc2[nt][3] * ns1);
        }
    }
}

// ---------------- SpMM 2 (pairwise HADD2, fp32 accumulate) ----------------
__global__ void k_spmm2(const float* __restrict__ b2, float* __restrict__ out, int n) {
    int w = (blockIdx.x * blockDim.x + threadIdx.x) >> 5;
    int lane = threadIdx.x & 31;
    if (w >= n) return;
    int beg = g_row_ptr[w];
    int end = g_row_ptr[w + 1];
    float2 acc = make_float2(0.f, 0.f);
    int ed = beg;
    for (; ed + 3 < end; ed += 4) {
        int s0 = g_csr_src[ed];
        int s1 = g_csr_src[ed + 1];
        int s2 = g_csr_src[ed + 2];
        int s3 = g_csr_src[ed + 3];
        __half2 t0 = g_t_h[(size_t)s0 * 32 + lane];
        __half2 t1 = g_t_h[(size_t)s1 * 32 + lane];
        __half2 t2 = g_t_h[(size_t)s2 * 32 + lane];
        __half2 t3 = g_t_h[(size_t)s3 * 32 + lane];
        float2 p01 = __half22float2(__hadd2(t0, t1));
        float2 p23 = __half22float2(__hadd2(t2, t3));
        acc.x += p01.x + p23.x;
        acc.y += p01.y + p23.y;
    }
    for (; ed < end; ed++) {
        int s0 = g_csr_src[ed];
        float2 v0 = __half22float2(g_t_h[(size_t)s0 * 32 + lane]);
        acc.x += v0.x;
        acc.y += v0.y;
    }
    float nd = g_norm_dst[w];
    float2 bb = ((const float2*)b2)[lane];
    float2 o;
    o.x = fmaf(acc.x, nd, bb.x);
    o.y = fmaf(acc.y, nd, bb.y);
    ((float2*)out)[(size_t)w * 32 + lane] = o;
}

// ---------------- launch ----------------
extern "C" void kernel_launch(void* const* d_in, const int* in_sizes, int n_in,
                              void* d_out, int out_size) {
    const int* src = (const int*)d_in[1];
    const int* dst = (const int*)d_in[2];
    const float* emb = (const float*)d_in[3];
    const float* W1  = (const float*)d_in[4];
    const float* b1  = (const float*)d_in[5];
    const float* W2  = (const float*)d_in[6];
    const float* b2  = (const float*)d_in[7];
    float* out = (float*)d_out;

    const int n = in_sizes[0];
    const int e = in_sizes[1];
    const int e2 = e >> 1;

    k_zero<<<(n + 255) / 256, 256>>>(n);
    k_degree<<<(e2 + 256) / 256, 256>>>(src, dst, e2, e);
    k_scan_partial<<<SCAN_NB, 256>>>(n);     // also computes norms
    k_prep<<<(n * 16 + 255) / 256, 256>>>(emb, n * 16);
    k_scan_blk<<<1, 128>>>(n, e);
    k_scan_final<<<SCAN_NB, 256>>>(n);
    k_fill<<<(e2 + 256) / 256, 256>>>(src, dst, e2, e);

    int warps_grid = (n * 32 + 255) / 256;
    k_spmm1<<<warps_grid, 256>>>(n);
    k_gemm_mma<<<(n + 63) / 64, 256>>>(W1, b1, W2, n);
    k_spmm2<<<warps_grid, 256>>>(b2, out, n);
}

// round 16
// speedup vs baseline: 1.2892x; 1.0652x over previous
#include <cuda_runtime.h>
#include <cuda_fp16.h>
#include <cstdint>

#define NN 100000
#define NE 1600000
#define SCAN_TILE 1024
#define SCAN_NB ((NN + SCAN_TILE - 1) / SCAN_TILE)   // 98

#define APAD 136   // row stride in halves (conflict-free for frag loads)
// dynamic smem layout: As[128*APAD] | W1t[128*APAD] | W2t[64*APAD] | b1s[128]
#define GEMM_SMEM_BYTES ((128 + 128 + 64) * APAD * 2 + 128 * 4)

// m16n8k16 fp16 MMA, fp32 accumulate
#define MMA16816(c0, c1, c2, c3, a0, a1, a2, a3, b0, b1) \
    asm volatile("mma.sync.aligned.m16n8k16.row.col.f32.f16.f16.f32 " \
        "{%0,%1,%2,%3}, {%4,%5,%6,%7}, {%8,%9}, {%0,%1,%2,%3};" \
        : "+f"(c0), "+f"(c1), "+f"(c2), "+f"(c3) \
        : "r"(a0), "r"(a1), "r"(a2), "r"(a3), "r"(b0), "r"(b1))

// ---------------- device scratch ----------------
__device__ int     g_deg_in[NN];
__device__ int     g_deg_out[NN];
__device__ int     g_cursor[NN];
__device__ float   g_norm_src[NN];
__device__ float   g_norm_dst[NN];
__device__ int     g_row_ptr[NN + 1];
__device__ int     g_csr_src[NE];
__device__ int     g_blk_sum[SCAN_NB];
__device__ int     g_blk_off[SCAN_NB];
__device__ __half2 g_emb_h[(size_t)NN * 64];
__device__ __half2 g_agg_h[(size_t)NN * 64];
__device__ __half2 g_t_h[(size_t)NN * 32];

// ---------------- setup ----------------
__global__ void k_zero(int n) {
    int i = blockIdx.x * blockDim.x + threadIdx.x;
    if (i < n) { g_deg_in[i] = 0; g_deg_out[i] = 0; g_cursor[i] = 0; }
}

__global__ void k_degree(const int* __restrict__ src,
                         const int* __restrict__ dst, int e2, int e) {
    int i = blockIdx.x * blockDim.x + threadIdx.x;
    if (i < e2) {
        int2 s = ((const int2*)src)[i];
        int2 d = ((const int2*)dst)[i];
        if ((unsigned)s.x < NN) atomicAdd(&g_deg_out[s.x], 1);
        if ((unsigned)s.y < NN) atomicAdd(&g_deg_out[s.y], 1);
        if ((unsigned)d.x < NN) atomicAdd(&g_deg_in[d.x], 1);
        if ((unsigned)d.y < NN) atomicAdd(&g_deg_in[d.y], 1);
    } else if (i == e2 && (e & 1)) {
        int s = src[e - 1], d = dst[e - 1];
        if ((unsigned)s < NN) atomicAdd(&g_deg_out[s], 1);
        if ((unsigned)d < NN) atomicAdd(&g_deg_in[d], 1);
    }
}

__global__ void k_prep(const float* __restrict__ emb, int n16) {
    int i = blockIdx.x * blockDim.x + threadIdx.x;
    if (i < n16) {
        int r = i >> 4;
        float4 v0 = ((const float4*)emb)[2 * i];
        float4 v1 = ((const float4*)emb)[2 * i + 1];
        float ns = g_norm_src[r];
        uint4 o;
        *(__half2*)&o.x = __floats2half2_rn(v0.x * ns, v0.y * ns);
        *(__half2*)&o.y = __floats2half2_rn(v0.z * ns, v0.w * ns);
        *(__half2*)&o.z = __floats2half2_rn(v1.x * ns, v1.y * ns);
        *(__half2*)&o.w = __floats2half2_rn(v1.z * ns, v1.w * ns);
        ((uint4*)g_emb_h)[i] = o;
    }
}

__global__ void __launch_bounds__(256)
k_scan_partial(int n) {
    __shared__ int sm[256];
    int t = threadIdx.x;
    int base = blockIdx.x * SCAN_TILE + t * 4;
    int s = 0;
#pragma unroll
    for (int j = 0; j < 4; j++) {
        int i = base + j;
        if (i < n) {
            int din = g_deg_in[i];
            s += din;
            int dout = g_deg_out[i];
            if (dout < 1) dout = 1;
            if (din  < 1) din  = 1;
            g_norm_src[i] = rsqrtf((float)dout);
            g_norm_dst[i] = rsqrtf((float)din);
        }
    }
    sm[t] = s;
    __syncthreads();
    for (int off = 128; off > 0; off >>= 1) {
        if (t < off) sm[t] += sm[t + off];
        __syncthreads();
    }
    if (t == 0) g_blk_sum[blockIdx.x] = sm[0];
}

__global__ void __launch_bounds__(128)
k_scan_blk(int n, int e) {
    __shared__ int sm[128];
    int t = threadIdx.x;
    int v = (t < SCAN_NB) ? g_blk_sum[t] : 0;
    sm[t] = v;
    __syncthreads();
    for (int off = 1; off < 128; off <<= 1) {
        int add = 0;
        if (t >= off) add = sm[t - off];
        __syncthreads();
        sm[t] += add;
        __syncthreads();
    }
    if (t < SCAN_NB) g_blk_off[t] = sm[t] - v;
    if (t == 0) g_row_ptr[n] = e;
}

__global__ void __launch_bounds__(256)
k_scan_final(int n) {
    __shared__ int sm[256];
    int t = threadIdx.x;
    int base = blockIdx.x * SCAN_TILE + t * 4;
    int d[4];
    int s = 0;
#pragma unroll
    for (int j = 0; j < 4; j++) {
        int i = base + j;
        d[j] = (i < n) ? g_deg_in[i] : 0;
        s += d[j];
    }
    sm[t] = s;
    __syncthreads();
    for (int off = 1; off < 256; off <<= 1) {
        int add = 0;
        if (t >= off) add = sm[t - off];
        __syncthreads();
        sm[t] += add;
        __syncthreads();
    }
    int run = g_blk_off[blockIdx.x] + sm[t] - s;
#pragma unroll
    for (int j = 0; j < 4; j++) {
        int i = base + j;
        if (i < n) g_row_ptr[i] = run;
        run += d[j];
    }
}

__global__ void k_fill(const int* __restrict__ src,
                       const int* __restrict__ dst, int e2, int e) {
    int i = blockIdx.x * blockDim.x + threadIdx.x;
    if (i < e2) {
        int2 s = ((const int2*)src)[i];
        int2 d = ((const int2*)dst)[i];
        if ((unsigned)d.x < NN && (unsigned)s.x < NN) {
            int pos = g_row_ptr[d.x] + atomicAdd(&g_cursor[d.x], 1);
            g_csr_src[pos] = s.x;
        }
        if ((unsigned)d.y < NN && (unsigned)s.y < NN) {
            int pos = g_row_ptr[d.y] + atomicAdd(&g_cursor[d.y], 1);
            g_csr_src[pos] = s.y;
        }
    } else if (i == e2 && (e & 1)) {
        int s = src[e - 1], d = dst[e - 1];
        if ((unsigned)d < NN && (unsigned)s < NN) {
            int pos = g_row_ptr[d] + atomicAdd(&g_cursor[d], 1);
            g_csr_src[pos] = s;
        }
    }
}

// ---------------- SpMM 1: pairwise HADD2 then fp32 accumulate ----------------
__global__ void k_spmm1(int n) {
    int w = (blockIdx.x * blockDim.x + threadIdx.x) >> 5;
    int lane = threadIdx.x & 31;
    if (w >= n) return;
    int beg = g_row_ptr[w];
    int end = g_row_ptr[w + 1];
    const uint2* eh = (const uint2*)g_emb_h;
    float4 acc = make_float4(0.f, 0.f, 0.f, 0.f);
    int ed = beg;
    for (; ed + 3 < end; ed += 4) {
        int s0 = g_csr_src[ed];
        int s1 = g_csr_src[ed + 1];
        int s2 = g_csr_src[ed + 2];
        int s3 = g_csr_src[ed + 3];
        uint2 v0 = eh[(size_t)s0 * 32 + lane];
        uint2 v1 = eh[(size_t)s1 * 32 + lane];
        uint2 v2 = eh[(size_t)s2 * 32 + lane];
        uint2 v3 = eh[(size_t)s3 * 32 + lane];
        __half2 px01 = __hadd2(*(__half2*)&v0.x, *(__half2*)&v1.x);
        __half2 py01 = __hadd2(*(__half2*)&v0.y, *(__half2*)&v1.y);
        __half2 px23 = __hadd2(*(__half2*)&v2.x, *(__half2*)&v3.x);
        __half2 py23 = __hadd2(*(__half2*)&v2.y, *(__half2*)&v3.y);
        float2 a01 = __half22float2(px01), b01 = __half22float2(py01);
        float2 a23 = __half22float2(px23), b23 = __half22float2(py23);
        acc.x += a01.x + a23.x;
        acc.y += a01.y + a23.y;
        acc.z += b01.x + b23.x;
        acc.w += b01.y + b23.y;
    }
    for (; ed < end; ed++) {
        int s0 = g_csr_src[ed];
        uint2 v0 = eh[(size_t)s0 * 32 + lane];
        float2 a0 = __half22float2(*(__half2*)&v0.x);
        float2 b0 = __half22float2(*(__half2*)&v0.y);
        acc.x += a0.x; acc.y += a0.y; acc.z += b0.x; acc.w += b0.y;
    }
    float nd = g_norm_dst[w];
    uint2 o;
    *(__half2*)&o.x = __floats2half2_rn(acc.x * nd, acc.y * nd);
    *(__half2*)&o.y = __floats2half2_rn(acc.z * nd, acc.w * nd);
    ((uint2*)g_agg_h)[(size_t)w * 32 + lane] = o;
}

// ---------------- fused GEMM via HMMA — all weights resident, 1 sync ----------
// 256 thr, 128 rows per block; warp w owns rows 16w..16w+15 (A, h1, output all
// warp-private) -> NO block syncs after the initial load barrier.
__global__ void __launch_bounds__(256)
k_gemm_mma(const float* __restrict__ W1, const float* __restrict__ b1,
           const float* __restrict__ W2, int n) {
    extern __shared__ __half smem[];
    __half* As  = smem;                    // 128*APAD
    __half* W1t = smem + 128 * APAD;       // 128*APAD  [n][k]
    __half* W2t = W1t + 128 * APAD;        // 64*APAD   [n][k]
    float*  b1s = (float*)(W2t + 64 * APAD);

    const int tid = threadIdx.x;
    const int lane = tid & 31;
    const int wid = tid >> 5;
    const int row0 = blockIdx.x * 128;
    const int m0 = wid * 16;
    const int r = lane >> 2;          // 0..7
    const int qc = (lane & 3) * 2;    // 0,2,4,6

    // load A tile (fp16), zero-pad OOB rows
    for (int i = tid; i < 128 * 32; i += 256) {
        int row = i >> 5, q = i & 31;
        int gr = row0 + row;
        uint2 v = make_uint2(0u, 0u);
        if (gr < n) v = ((const uint2*)g_agg_h)[(size_t)gr * 32 + q];
        *(uint2*)&As[row * APAD + q * 4] = v;
    }
    // load W1^T (coalesced global reads)
    for (int i = tid; i < 128 * 128; i += 256) {
        int kk = i >> 7, nn = i & 127;
        W1t[nn * APAD + kk] = __float2half(W1[i]);
    }
    // load W2^T
    for (int i = tid; i < 128 * 64; i += 256) {
        int kk = i >> 6, nn = i & 63;
        W2t[nn * APAD + kk] = __float2half(W2[i]);
    }
    if (tid < 128) b1s[tid] = b1[tid];
    __syncthreads();   // the ONLY block barrier

    // ---- phase 1: 16x128 per warp, K=128, fully resident ----
    float acc[16][4];
#pragma unroll
    for (int t2 = 0; t2 < 16; t2++)
#pragma unroll
        for (int j = 0; j < 4; j++) acc[t2][j] = 0.f;

#pragma unroll
    for (int ks = 0; ks < 8; ks++) {
        int kb = ks * 16;
        uint32_t a0 = *(uint32_t*)&As[(m0 + r) * APAD + kb + qc];
        uint32_t a1 = *(uint32_t*)&As[(m0 + r + 8) * APAD + kb + qc];
        uint32_t a2 = *(uint32_t*)&As[(m0 + r) * APAD + kb + qc + 8];
        uint32_t a3 = *(uint32_t*)&As[(m0 + r + 8) * APAD + kb + qc + 8];
#pragma unroll
        for (int nt = 0; nt < 16; nt++) {
            uint32_t b0 = *(uint32_t*)&W1t[(nt * 8 + r) * APAD + kb + qc];
            uint32_t b1f = *(uint32_t*)&W1t[(nt * 8 + r) * APAD + kb + qc + 8];
            MMA16816(acc[nt][0], acc[nt][1], acc[nt][2], acc[nt][3],
                     a0, a1, a2, a3, b0, b1f);
        }
    }

    // epilogue 1: relu + bias, h1 fp16 into As (warp-private rows, no sync)
#pragma unroll
    for (int nt = 0; nt < 16; nt++) {
        int c = nt * 8 + qc;
        float x0 = fmaxf(acc[nt][0] + b1s[c],     0.f);
        float x1 = fmaxf(acc[nt][1] + b1s[c + 1], 0.f);
        float x2 = fmaxf(acc[nt][2] + b1s[c],     0.f);
        float x3 = fmaxf(acc[nt][3] + b1s[c + 1], 0.f);
        *(__half2*)&As[(m0 + r) * APAD + c]     = __floats2half2_rn(x0, x1);
        *(__half2*)&As[(m0 + r + 8) * APAD + c] = __floats2half2_rn(x2, x3);
    }

    // ---- phase 2: 16x64 per warp, K=128 ----
    float acc2[8][4];
#pragma unroll
    for (int t2 = 0; t2 < 8; t2++)
#pragma unroll
        for (int j = 0; j < 4; j++) acc2[t2][j] = 0.f;

#pragma unroll
    for (int ks = 0; ks < 8; ks++) {
        int kb = ks * 16;
        uint32_t a0 = *(uint32_t*)&As[(m0 + r) * APAD + kb + qc];
        uint32_t a1 = *(uint32_t*)&As[(m0 + r + 8) * APAD + kb + qc];
        uint32_t a2 = *(uint32_t*)&As[(m0 + r) * APAD + kb + qc + 8];
        uint32_t a3 = *(uint32_t*)&As[(m0 + r + 8) * APAD + kb + qc + 8];
#pragma unroll
        for (int nt = 0; nt < 8; nt++) {
            uint32_t b0 = *(uint32_t*)&W2t[(nt * 8 + r) * APAD + kb + qc];
            uint32_t b1f = *(uint32_t*)&W2t[(nt * 8 + r) * APAD + kb + qc + 8];
            MMA16816(acc2[nt][0], acc2[nt][1], acc2[nt][2], acc2[nt][3],
                     a0, a1, a2, a3, b0, b1f);
        }
    }

    // epilogue 2: * norm_src, fp16 store
    {
        int gr0 = row0 + m0 + r;
        int gr1 = gr0 + 8;
        float ns0 = (gr0 < n) ? g_norm_src[gr0] : 0.f;
        float ns1 = (gr1 < n) ? g_norm_src[gr1] : 0.f;
#pragma unroll
        for (int nt = 0; nt < 8; nt++) {
            int c = nt * 8 + qc;   // even
            if (gr0 < n)
                g_t_h[(size_t)gr0 * 32 + (c >> 1)] =
                    __floats2half2_rn(acc2[nt][0] * ns0, acc2[nt][1] * ns0);
            if (gr1 < n)
                g_t_h[(size_t)gr1 * 32 + (c >> 1)] =
                    __floats2half2_rn(acc2[nt][2] * ns1, acc2[nt][3] * ns1);
        }
    }
}

// ---------------- SpMM 2 (pairwise HADD2, fp32 accumulate) ----------------
__global__ void k_spmm2(const float* __restrict__ b2, float* __restrict__ out, int n) {
    int w = (blockIdx.x * blockDim.x + threadIdx.x) >> 5;
    int lane = threadIdx.x & 31;
    if (w >= n) return;
    int beg = g_row_ptr[w];
    int end = g_row_ptr[w + 1];
    float2 acc = make_float2(0.f, 0.f);
    int ed = beg;
    for (; ed + 3 < end; ed += 4) {
        int s0 = g_csr_src[ed];
        int s1 = g_csr_src[ed + 1];
        int s2 = g_csr_src[ed + 2];
        int s3 = g_csr_src[ed + 3];
        __half2 t0 = g_t_h[(size_t)s0 * 32 + lane];
        __half2 t1 = g_t_h[(size_t)s1 * 32 + lane];
        __half2 t2 = g_t_h[(size_t)s2 * 32 + lane];
        __half2 t3 = g_t_h[(size_t)s3 * 32 + lane];
        float2 p01 = __half22float2(__hadd2(t0, t1));
        float2 p23 = __half22float2(__hadd2(t2, t3));
        acc.x += p01.x + p23.x;
        acc.y += p01.y + p23.y;
    }
    for (; ed < end; ed++) {
        int s0 = g_csr_src[ed];
        float2 v0 = __half22float2(g_t_h[(size_t)s0 * 32 + lane]);
        acc.x += v0.x;
        acc.y += v0.y;
    }
    float nd = g_norm_dst[w];
    float2 bb = ((const float2*)b2)[lane];
    float2 o;
    o.x = fmaf(acc.x, nd, bb.x);
    o.y = fmaf(acc.y, nd, bb.y);
    ((float2*)out)[(size_t)w * 32 + lane] = o;
}

// ---------------- launch ----------------
extern "C" void kernel_launch(void* const* d_in, const int* in_sizes, int n_in,
                              void* d_out, int out_size) {
    const int* src = (const int*)d_in[1];
    const int* dst = (const int*)d_in[2];
    const float* emb = (const float*)d_in[3];
    const float* W1  = (const float*)d_in[4];
    const float* b1  = (const float*)d_in[5];
    const float* W2  = (const float*)d_in[6];
    const float* b2  = (const float*)d_in[7];
    float* out = (float*)d_out;

    const int n = in_sizes[0];
    const int e = in_sizes[1];
    const int e2 = e >> 1;

    static bool attr_set = false;
    if (!attr_set) {
        cudaFuncSetAttribute(k_gemm_mma,
                             cudaFuncAttributeMaxDynamicSharedMemorySize,
                             GEMM_SMEM_BYTES);
        attr_set = true;
    }

    k_zero<<<(n + 255) / 256, 256>>>(n);
    k_degree<<<(e2 + 256) / 256, 256>>>(src, dst, e2, e);
    k_scan_partial<<<SCAN_NB, 256>>>(n);     // also computes norms
    k_prep<<<(n * 16 + 255) / 256, 256>>>(emb, n * 16);
    k_scan_blk<<<1, 128>>>(n, e);
    k_scan_final<<<SCAN_NB, 256>>>(n);
    k_fill<<<(e2 + 256) / 256, 256>>>(src, dst, e2, e);

    int warps_grid = (n * 32 + 255) / 256;
    k_spmm1<<<warps_grid, 256>>>(n);
    k_gemm_mma<<<(n + 127) / 128, 256, GEMM_SMEM_BYTES>>>(W1, b1, W2, n);
    k_spmm2<<<warps_grid, 256>>>(b2, out, n);
}

// round 17
// speedup vs baseline: 1.3630x; 1.0573x over previous
#include <cuda_runtime.h>
#include <cuda_fp16.h>
#include <cstdint>

#define NN 100000
#define NE 1600000
#define SCAN_TILE 1024
#define SCAN_NB ((NN + SCAN_TILE - 1) / SCAN_TILE)   // 98

#define APAD 136   // W row stride in halves (conflict-free B-frag LDS)
// dynamic smem: W1t[128*APAD] | W2t[64*APAD] | b1s[128]
#define GEMM_SMEM_BYTES ((128 + 64) * APAD * 2 + 128 * 4)

// m16n8k16 fp16 MMA, fp32 accumulate
#define MMA16816(c0, c1, c2, c3, a0, a1, a2, a3, b0, b1) \
    asm volatile("mma.sync.aligned.m16n8k16.row.col.f32.f16.f16.f32 " \
        "{%0,%1,%2,%3}, {%4,%5,%6,%7}, {%8,%9}, {%0,%1,%2,%3};" \
        : "+f"(c0), "+f"(c1), "+f"(c2), "+f"(c3) \
        : "r"(a0), "r"(a1), "r"(a2), "r"(a3), "r"(b0), "r"(b1))

// ---------------- device scratch ----------------
__device__ int     g_deg_in[NN];
__device__ int     g_deg_out[NN];
__device__ int     g_cursor[NN];
__device__ float   g_norm_src[NN];
__device__ float   g_norm_dst[NN];
__device__ int     g_row_ptr[NN + 1];
__device__ int     g_csr_src[NE];
__device__ int     g_blk_sum[SCAN_NB];
__device__ int     g_blk_off[SCAN_NB];
__device__ __half2 g_emb_h[(size_t)NN * 64];
__device__ __half2 g_agg_h[(size_t)NN * 64];
__device__ __half2 g_t_h[(size_t)NN * 32];

// ---------------- setup ----------------
__global__ void k_zero(int n) {
    int i = blockIdx.x * blockDim.x + threadIdx.x;
    if (i < n) { g_deg_in[i] = 0; g_deg_out[i] = 0; g_cursor[i] = 0; }
}

__global__ void k_degree(const int* __restrict__ src,
                         const int* __restrict__ dst, int e2, int e) {
    int i = blockIdx.x * blockDim.x + threadIdx.x;
    if (i < e2) {
        int2 s = ((const int2*)src)[i];
        int2 d = ((const int2*)dst)[i];
        if ((unsigned)s.x < NN) atomicAdd(&g_deg_out[s.x], 1);
        if ((unsigned)s.y < NN) atomicAdd(&g_deg_out[s.y], 1);
        if ((unsigned)d.x < NN) atomicAdd(&g_deg_in[d.x], 1);
        if ((unsigned)d.y < NN) atomicAdd(&g_deg_in[d.y], 1);
    } else if (i == e2 && (e & 1)) {
        int s = src[e - 1], d = dst[e - 1];
        if ((unsigned)s < NN) atomicAdd(&g_deg_out[s], 1);
        if ((unsigned)d < NN) atomicAdd(&g_deg_in[d], 1);
    }
}

__global__ void k_prep(const float* __restrict__ emb, int n16) {
    int i = blockIdx.x * blockDim.x + threadIdx.x;
    if (i < n16) {
        int r = i >> 4;
        float4 v0 = ((const float4*)emb)[2 * i];
        float4 v1 = ((const float4*)emb)[2 * i + 1];
        float ns = g_norm_src[r];
        uint4 o;
        *(__half2*)&o.x = __floats2half2_rn(v0.x * ns, v0.y * ns);
        *(__half2*)&o.y = __floats2half2_rn(v0.z * ns, v0.w * ns);
        *(__half2*)&o.z = __floats2half2_rn(v1.x * ns, v1.y * ns);
        *(__half2*)&o.w = __floats2half2_rn(v1.z * ns, v1.w * ns);
        ((uint4*)g_emb_h)[i] = o;
    }
}

__global__ void __launch_bounds__(256)
k_scan_partial(int n) {
    __shared__ int sm[256];
    int t = threadIdx.x;
    int base = blockIdx.x * SCAN_TILE + t * 4;
    int s = 0;
#pragma unroll
    for (int j = 0; j < 4; j++) {
        int i = base + j;
        if (i < n) {
            int din = g_deg_in[i];
            s += din;
            int dout = g_deg_out[i];
            if (dout < 1) dout = 1;
            if (din  < 1) din  = 1;
            g_norm_src[i] = rsqrtf((float)dout);
            g_norm_dst[i] = rsqrtf((float)din);
        }
    }
    sm[t] = s;
    __syncthreads();
    for (int off = 128; off > 0; off >>= 1) {
        if (t < off) sm[t] += sm[t + off];
        __syncthreads();
    }
    if (t == 0) g_blk_sum[blockIdx.x] = sm[0];
}

__global__ void __launch_bounds__(128)
k_scan_blk(int n, int e) {
    __shared__ int sm[128];
    int t = threadIdx.x;
    int v = (t < SCAN_NB) ? g_blk_sum[t] : 0;
    sm[t] = v;
    __syncthreads();
    for (int off = 1; off < 128; off <<= 1) {
        int add = 0;
        if (t >= off) add = sm[t - off];
        __syncthreads();
        sm[t] += add;
        __syncthreads();
    }
    if (t < SCAN_NB) g_blk_off[t] = sm[t] - v;
    if (t == 0) g_row_ptr[n] = e;
}

__global__ void __launch_bounds__(256)
k_scan_final(int n) {
    __shared__ int sm[256];
    int t = threadIdx.x;
    int base = blockIdx.x * SCAN_TILE + t * 4;
    int d[4];
    int s = 0;
#pragma unroll
    for (int j = 0; j < 4; j++) {
        int i = base + j;
        d[j] = (i < n) ? g_deg_in[i] : 0;
        s += d[j];
    }
    sm[t] = s;
    __syncthreads();
    for (int off = 1; off < 256; off <<= 1) {
        int add = 0;
        if (t >= off) add = sm[t - off];
        __syncthreads();
        sm[t] += add;
        __syncthreads();
    }
    int run = g_blk_off[blockIdx.x] + sm[t] - s;
#pragma unroll
    for (int j = 0; j < 4; j++) {
        int i = base + j;
        if (i < n) g_row_ptr[i] = run;
        run += d[j];
    }
}

__global__ void k_fill(const int* __restrict__ src,
                       const int* __restrict__ dst, int e2, int e) {
    int i = blockIdx.x * blockDim.x + threadIdx.x;
    if (i < e2) {
        int2 s = ((const int2*)src)[i];
        int2 d = ((const int2*)dst)[i];
        if ((unsigned)d.x < NN && (unsigned)s.x < NN) {
            int pos = g_row_ptr[d.x] + atomicAdd(&g_cursor[d.x], 1);
            g_csr_src[pos] = s.x;
        }
        if ((unsigned)d.y < NN && (unsigned)s.y < NN) {
            int pos = g_row_ptr[d.y] + atomicAdd(&g_cursor[d.y], 1);
            g_csr_src[pos] = s.y;
        }
    } else if (i == e2 && (e & 1)) {
        int s = src[e - 1], d = dst[e - 1];
        if ((unsigned)d < NN && (unsigned)s < NN) {
            int pos = g_row_ptr[d] + atomicAdd(&g_cursor[d], 1);
            g_csr_src[pos] = s;
        }
    }
}

// ---------------- SpMM 1: pairwise HADD2 then fp32 accumulate ----------------
__global__ void k_spmm1(int n) {
    int w = (blockIdx.x * blockDim.x + threadIdx.x) >> 5;
    int lane = threadIdx.x & 31;
    if (w >= n) return;
    int beg = g_row_ptr[w];
    int end = g_row_ptr[w + 1];
    const uint2* eh = (const uint2*)g_emb_h;
    float4 acc = make_float4(0.f, 0.f, 0.f, 0.f);
    int ed = beg;
    for (; ed + 3 < end; ed += 4) {
        int s0 = g_csr_src[ed];
        int s1 = g_csr_src[ed + 1];
        int s2 = g_csr_src[ed + 2];
        int s3 = g_csr_src[ed + 3];
        uint2 v0 = eh[(size_t)s0 * 32 + lane];
        uint2 v1 = eh[(size_t)s1 * 32 + lane];
        uint2 v2 = eh[(size_t)s2 * 32 + lane];
        uint2 v3 = eh[(size_t)s3 * 32 + lane];
        __half2 px01 = __hadd2(*(__half2*)&v0.x, *(__half2*)&v1.x);
        __half2 py01 = __hadd2(*(__half2*)&v0.y, *(__half2*)&v1.y);
        __half2 px23 = __hadd2(*(__half2*)&v2.x, *(__half2*)&v3.x);
        __half2 py23 = __hadd2(*(__half2*)&v2.y, *(__half2*)&v3.y);
        float2 a01 = __half22float2(px01), b01 = __half22float2(py01);
        float2 a23 = __half22float2(px23), b23 = __half22float2(py23);
        acc.x += a01.x + a23.x;
        acc.y += a01.y + a23.y;
        acc.z += b01.x + b23.x;
        acc.w += b01.y + b23.y;
    }
    for (; ed < end; ed++) {
        int s0 = g_csr_src[ed];
        uint2 v0 = eh[(size_t)s0 * 32 + lane];
        float2 a0 = __half22float2(*(__half2*)&v0.x);
        float2 b0 = __half22float2(*(__half2*)&v0.y);
        acc.x += a0.x; acc.y += a0.y; acc.z += b0.x; acc.w += b0.y;
    }
    float nd = g_norm_dst[w];
    uint2 o;
    *(__half2*)&o.x = __floats2half2_rn(acc.x * nd, acc.y * nd);
    *(__half2*)&o.y = __floats2half2_rn(acc.z * nd, acc.w * nd);
    ((uint2*)g_agg_h)[(size_t)w * 32 + lane] = o;
}

// ---------------- fused GEMM via HMMA — register-resident A and h1 ------------
// 512 thr (16 warps), 256 rows per block; warp w owns rows 16w..16w+15.
// A-fragments loaded straight from g_agg_h into registers (no As smem).
// Phase-1 C-fragments ARE phase-2 A-fragments (m16n8k16 layout identity):
// relu+bias+fp16-pack entirely in registers. SMEM holds only W1^T, W2^T, b1.
__global__ void __launch_bounds__(512)
k_gemm_mma(const float* __restrict__ W1, const float* __restrict__ b1,
           const float* __restrict__ W2, int n) {
    extern __shared__ __half smem[];
    __half* W1t = smem;                    // 128*APAD  [n][k]
    __half* W2t = W1t + 128 * APAD;        // 64*APAD   [n][k]
    float*  b1s = (float*)(W2t + 64 * APAD);

    const int tid = threadIdx.x;
    const int lane = tid & 31;
    const int wid = tid >> 5;              // 0..15
    const int row0 = blockIdx.x * 256;
    const int m0 = wid * 16;
    const int r = lane >> 2;               // 0..7
    const int q = lane & 3;                // uint32 col within 8-half group
    const int qc = q * 2;                  // 0,2,4,6

    // ---- fill W1^T, W2^T (coalesced LDG; k-major -> n-major transpose) ----
    for (int i = tid; i < 128 * 128; i += 512) {
        int kk = i >> 7, nn = i & 127;
        W1t[nn * APAD + kk] = __float2half(W1[i]);
    }
    for (int i = tid; i < 128 * 64; i += 512) {
        int kk = i >> 6, nn = i & 63;
        W2t[nn * APAD + kk] = __float2half(W2[i]);
    }
    if (tid < 128) b1s[tid] = b1[tid];

    // ---- A fragments direct from gmem (warp-private rows, no smem) ----
    const int ra = row0 + m0 + r;
    const int rb = ra + 8;
    const uint32_t* aga = (const uint32_t*)g_agg_h;   // row = 64 uint32
    uint32_t aF[8][4];
#pragma unroll
    for (int ks = 0; ks < 8; ks++) {
        aF[ks][0] = aF[ks][1] = aF[ks][2] = aF[ks][3] = 0u;
        if (ra < n) {
            aF[ks][0] = aga[ra * 64 + ks * 8 + q];
            aF[ks][2] = aga[ra * 64 + ks * 8 + 4 + q];
        }
        if (rb < n) {
            aF[ks][1] = aga[rb * 64 + ks * 8 + q];
            aF[ks][3] = aga[rb * 64 + ks * 8 + 4 + q];
        }
    }
    __syncthreads();   // weights ready

    // ---- phase 1: 16x128 per warp, K=128 ----
    float acc[16][4];
#pragma unroll
    for (int t2 = 0; t2 < 16; t2++)
#pragma unroll
        for (int j = 0; j < 4; j++) acc[t2][j] = 0.f;

#pragma unroll
    for (int ks = 0; ks < 8; ks++) {
        int kb = ks * 16;
#pragma unroll
        for (int nt = 0; nt < 16; nt++) {
            uint32_t b0 = *(uint32_t*)&W1t[(nt * 8 + r) * APAD + kb + qc];
            uint32_t b1f = *(uint32_t*)&W1t[(nt * 8 + r) * APAD + kb + qc + 8];
            MMA16816(acc[nt][0], acc[nt][1], acc[nt][2], acc[nt][3],
                     aF[ks][0], aF[ks][1], aF[ks][2], aF[ks][3], b0, b1f);
        }
    }

    // ---- epilogue 1 in registers: relu+bias, pack fp16 -> phase-2 A frags ----
    // phase-2 frag[ks2] = { pack(acc[2ks2][0..1]), pack(acc[2ks2][2..3]),
    //                       pack(acc[2ks2+1][0..1]), pack(acc[2ks2+1][2..3]) }
    uint32_t hF[8][4];
#pragma unroll
    for (int ks2 = 0; ks2 < 8; ks2++) {
#pragma unroll
        for (int half = 0; half < 2; half++) {
            int nt = 2 * ks2 + half;
            float2 bb = *(const float2*)(b1s + nt * 8 + qc);
            float x0 = fmaxf(acc[nt][0] + bb.x, 0.f);
            float x1 = fmaxf(acc[nt][1] + bb.y, 0.f);
            float x2 = fmaxf(acc[nt][2] + bb.x, 0.f);
            float x3 = fmaxf(acc[nt][3] + bb.y, 0.f);
            __half2 lo = __floats2half2_rn(x0, x1);
            __half2 hi = __floats2half2_rn(x2, x3);
            hF[ks2][2 * half]     = *(uint32_t*)&lo;
            hF[ks2][2 * half + 1] = *(uint32_t*)&hi;
        }
    }

    // ---- phase 2: 16x64 per warp, K=128 ----
    float acc2[8][4];
#pragma unroll
    for (int t2 = 0; t2 < 8; t2++)
#pragma unroll
        for (int j = 0; j < 4; j++) acc2[t2][j] = 0.f;

#pragma unroll
    for (int ks = 0; ks < 8; ks++) {
        int kb = ks * 16;
#pragma unroll
        for (int nt = 0; nt < 8; nt++) {
            uint32_t b0 = *(uint32_t*)&W2t[(nt * 8 + r) * APAD + kb + qc];
            uint32_t b1f = *(uint32_t*)&W2t[(nt * 8 + r) * APAD + kb + qc + 8];
            MMA16816(acc2[nt][0], acc2[nt][1], acc2[nt][2], acc2[nt][3],
                     hF[ks][0], hF[ks][1], hF[ks][2], hF[ks][3], b0, b1f);
        }
    }

    // ---- epilogue 2: * norm_src, fp16 store ----
    {
        float ns0 = (ra < n) ? g_norm_src[ra] : 0.f;
        float ns1 = (rb < n) ? g_norm_src[rb] : 0.f;
#pragma unroll
        for (int nt = 0; nt < 8; nt++) {
            int c = nt * 8 + qc;   // even
            if (ra < n)
                g_t_h[(size_t)ra * 32 + (c >> 1)] =
                    __floats2half2_rn(acc2[nt][0] * ns0, acc2[nt][1] * ns0);
            if (rb < n)
                g_t_h[(size_t)rb * 32 + (c >> 1)] =
                    __floats2half2_rn(acc2[nt][2] * ns1, acc2[nt][3] * ns1);
        }
    }
}

// ---------------- SpMM 2 (pairwise HADD2, fp32 accumulate) ----------------
__global__ void k_spmm2(const float* __restrict__ b2, float* __restrict__ out, int n) {
    int w = (blockIdx.x * blockDim.x + threadIdx.x) >> 5;
    int lane = threadIdx.x & 31;
    if (w >= n) return;
    int beg = g_row_ptr[w];
    int end = g_row_ptr[w + 1];
    float2 acc = make_float2(0.f, 0.f);
    int ed = beg;
    for (; ed + 3 < end; ed += 4) {
        int s0 = g_csr_src[ed];
        int s1 = g_csr_src[ed + 1];
        int s2 = g_csr_src[ed + 2];
        int s3 = g_csr_src[ed + 3];
        __half2 t0 = g_t_h[(size_t)s0 * 32 + lane];
        __half2 t1 = g_t_h[(size_t)s1 * 32 + lane];
        __half2 t2 = g_t_h[(size_t)s2 * 32 + lane];
        __half2 t3 = g_t_h[(size_t)s3 * 32 + lane];
        float2 p01 = __half22float2(__hadd2(t0, t1));
        float2 p23 = __half22float2(__hadd2(t2, t3));
        acc.x += p01.x + p23.x;
        acc.y += p01.y + p23.y;
    }
    for (; ed < end; ed++) {
        int s0 = g_csr_src[ed];
        float2 v0 = __half22float2(g_t_h[(size_t)s0 * 32 + lane]);
        acc.x += v0.x;
        acc.y += v0.y;
    }
    float nd = g_norm_dst[w];
    float2 bb = ((const float2*)b2)[lane];
    float2 o;
    o.x = fmaf(acc.x, nd, bb.x);
    o.y = fmaf(acc.y, nd, bb.y);
    ((float2*)out)[(size_t)w * 32 + lane] = o;
}

// ---------------- launch ----------------
extern "C" void kernel_launch(void* const* d_in, const int* in_sizes, int n_in,
                              void* d_out, int out_size) {
    const int* src = (const int*)d_in[1];
    const int* dst = (const int*)d_in[2];
    const float* emb = (const float*)d_in[3];
    const float* W1  = (const float*)d_in[4];
    const float* b1  = (const float*)d_in[5];
    const float* W2  = (const float*)d_in[6];
    const float* b2  = (const float*)d_in[7];
    float* out = (float*)d_out;

    const int n = in_sizes[0];
    const int e = in_sizes[1];
    const int e2 = e >> 1;

    static bool attr_set = false;
    if (!attr_set) {
        cudaFuncSetAttribute(k_gemm_mma,
                             cudaFuncAttributeMaxDynamicSharedMemorySize,
                             GEMM_SMEM_BYTES);
        attr_set = true;
    }

    k_zero<<<(n + 255) / 256, 256>>>(n);
    k_degree<<<(e2 + 256) / 256, 256>>>(src, dst, e2, e);
    k_scan_partial<<<SCAN_NB, 256>>>(n);     // also computes norms
    k_prep<<<(n * 16 + 255) / 256, 256>>>(emb, n * 16);
    k_scan_blk<<<1, 128>>>(n, e);
    k_scan_final<<<SCAN_NB, 256>>>(n);
    k_fill<<<(e2 + 256) / 256, 256>>>(src, dst, e2, e);

    int warps_grid = (n * 32 + 255) / 256;
    k_spmm1<<<warps_grid, 256>>>(n);
    k_gemm_mma<<<(n + 255) / 256, 512, GEMM_SMEM_BYTES>>>(W1, b1, W2, n);
    k_spmm2<<<warps_grid, 256>>>(b2, out, n);
}